// round 3
// baseline (speedup 1.0000x reference)
#include <cuda_runtime.h>
#include <cuda_bf16.h>

// ---------------------------------------------------------------------------
// Problem constants: B=4, C=128, T=1024, F=128, H=16
// Pipeline:
//   qkv = conv3x3(query, in_w, in_b)           [B,48,T,F]
//   q,k,v = split; q *= C^-0.5; relu all       -> [BH=64, T, F]
//   aw_t = softmax(q k^T)                      [64, 1024, 1024]
//   attn_t = aw_t v                            -> attn[:, 0:16]
//   aw_f = softmax(q^T k)                      [64, 128, 128]
//   attn_f = (aw_f v^T)^T = v aw_f^T           -> attn[:, 16:32]
//   out = relu(conv3x3(attn, out_w, out_b))    [B,128,T,F]  -> d_out[0 : 67108864]
//   aw_avg = mean_h aw_t                       [B,T,T]      -> d_out[67108864 : ]
// ---------------------------------------------------------------------------

#define Bsz 4
#define Hh  16
#define Tt  1024
#define Ff  128
#define BH  64

static const float SCALING = 0.08838834764831845f; // 128^-0.5

// scratch (device globals: allocation-free)
__device__ float g_q   [(long)BH * Tt * Ff];
__device__ float g_k   [(long)BH * Tt * Ff];
__device__ float g_v   [(long)BH * Tt * Ff];
__device__ float g_aw  [(long)BH * Tt * Tt];     // 268 MB
__device__ float g_attn[(long)Bsz * 32 * Tt * Ff];
__device__ float g_pf  [(long)BH * Ff * Ff];

// ---------------------------------------------------------------------------
// Direct 3x3 conv, padding 1. Tile: 16(T) x 64(F), 16 output channels per
// block, 8-input-channel smem chunks. 256 threads; thread = (ty, tx) computes
// 4 consecutive F pixels for 16 couts.
// EPI 0: qkv epilogue (group g: 0->q scaled, 1->k, 2->v; relu) to outA/B/C
// EPI 1: relu(acc+bias) to outA laid out [B,128,T,F]
// ---------------------------------------------------------------------------
template<int CIN, int NG, int EPI>
__global__ void __launch_bounds__(256, 2)
conv3x3_kernel(const float* __restrict__ in, const float* __restrict__ w,
               const float* __restrict__ bias,
               float* __restrict__ outA, float* __restrict__ outB,
               float* __restrict__ outC)
{
    __shared__ float s_in[8][18][68];
    __shared__ float s_w[8 * 9 * 16];

    const int tid = threadIdx.x;
    const int tx = tid & 15;        // F quad
    const int ty = tid >> 4;        // T row
    const int f0 = blockIdx.x * 64;
    const int t0 = blockIdx.y * 16;
    const int b  = blockIdx.z / NG;
    const int g  = blockIdx.z % NG;
    const int g16 = g * 16;

    float acc[16][4];
#pragma unroll
    for (int i = 0; i < 16; i++)
#pragma unroll
        for (int j = 0; j < 4; j++) acc[i][j] = 0.f;

    for (int cb = 0; cb < CIN; cb += 8) {
        __syncthreads();
        // load input chunk with halo (zero-pad borders)
        for (int idx = tid; idx < 8 * 18 * 66; idx += 256) {
            int cc  = idx / 1188;
            int rem = idx - cc * 1188;
            int r   = rem / 66;
            int col = rem - r * 66;
            int ti = t0 + r - 1;
            int fi = f0 + col - 1;
            float val = 0.f;
            if ((unsigned)ti < (unsigned)Tt && (unsigned)fi < (unsigned)Ff)
                val = in[(((long)b * CIN + cb + cc) * Tt + ti) * Ff + fi];
            s_in[cc][r][col] = val;
        }
        // load weights: s_w[(cc*9 + tap)*16 + co]
        for (int idx = tid; idx < 8 * 9 * 16; idx += 256) {
            int co  = idx & 15;
            int rem = idx >> 4;
            int cc  = rem / 9;
            int tap = rem - cc * 9;
            s_w[idx] = w[(((long)(g16 + co)) * CIN + cb + cc) * 9 + tap];
        }
        __syncthreads();

#pragma unroll 1
        for (int cc = 0; cc < 8; cc++) {
#pragma unroll
            for (int kt = 0; kt < 3; kt++) {
                float4 p  = *(const float4*)&s_in[cc][ty + kt][tx * 4];
                float4 p2 = *(const float4*)&s_in[cc][ty + kt][tx * 4 + 4];
                float iv[6] = {p.x, p.y, p.z, p.w, p2.x, p2.y};
#pragma unroll
                for (int kf = 0; kf < 3; kf++) {
                    const float* wp = &s_w[((cc * 3 + kt) * 3 + kf) * 16];
#pragma unroll
                    for (int co = 0; co < 16; co++) {
                        float wv = wp[co];
                        acc[co][0] += iv[kf + 0] * wv;
                        acc[co][1] += iv[kf + 1] * wv;
                        acc[co][2] += iv[kf + 2] * wv;
                        acc[co][3] += iv[kf + 3] * wv;
                    }
                }
            }
        }
    }

    const int t = t0 + ty;
    const long fb = f0 + tx * 4;

    if (EPI == 0) {
        float* dst = (g == 0) ? outA : (g == 1) ? outB : outC;
        const float sc = (g == 0) ? SCALING : 1.f;
#pragma unroll
        for (int co = 0; co < 16; co++) {
            float bv = bias[g16 + co];
            float4 r;
            r.x = fmaxf((acc[co][0] + bv) * sc, 0.f);
            r.y = fmaxf((acc[co][1] + bv) * sc, 0.f);
            r.z = fmaxf((acc[co][2] + bv) * sc, 0.f);
            r.w = fmaxf((acc[co][3] + bv) * sc, 0.f);
            *(float4*)(dst + (((long)(b * Hh + co)) * Tt + t) * Ff + fb) = r;
        }
    } else {
#pragma unroll
        for (int co = 0; co < 16; co++) {
            float bv = bias[g16 + co];
            float4 r;
            r.x = fmaxf(acc[co][0] + bv, 0.f);
            r.y = fmaxf(acc[co][1] + bv, 0.f);
            r.z = fmaxf(acc[co][2] + bv, 0.f);
            r.w = fmaxf(acc[co][3] + bv, 0.f);
            *(float4*)(outA + (((long)b * 128 + g16 + co) * Tt + t) * Ff + fb) = r;
        }
    }
}

// ---------------------------------------------------------------------------
// Batched SGEMM: C[m][n] = sum_k A_l[m][k] * B_l[k][n]
//   TA: A physical is [k][m] (lda along k-rows); else A[m][k]
//   TB: B physical is [n][k]; else B[k][n]
// Tile 64x64x32, 256 threads, 4x4 microtile.
// CMODE 0: C = Cbase + z*sC (row stride ldc)
// CMODE 1: attention epilogue -> g_attn[(b*32 + chOff + h)][m][n], ldc = 128
// ---------------------------------------------------------------------------
template<bool TA, bool TB, int CMODE>
__global__ void __launch_bounds__(256)
gemm64_kernel(const float* __restrict__ A, const float* __restrict__ B,
              float* __restrict__ C,
              int M, int N, int K, int lda, int ldb, int ldc,
              long sA, long sB, long sC, int chOff)
{
    constexpr int BM = 64, BN = 64, BK = 32;
    __shared__ float sa[BK][BM + 4];
    __shared__ float sb[BK][BN + 4];

    const int z = blockIdx.z;
    const float* Ab = A + (long)z * sA;
    const float* Bb = B + (long)z * sB;
    float* Cb;
    if (CMODE == 0) {
        Cb = C + (long)z * sC;
    } else {
        int b = z >> 4, h = z & 15;
        Cb = C + ((long)(b * 32 + chOff + h)) * Tt * Ff;
    }

    const int n0 = blockIdx.x * BN;
    const int m0 = blockIdx.y * BM;
    const int tid = threadIdx.x;
    const int tm = tid >> 4;
    const int tn = tid & 15;

    float acc[4][4];
#pragma unroll
    for (int i = 0; i < 4; i++)
#pragma unroll
        for (int j = 0; j < 4; j++) acc[i][j] = 0.f;

    for (int kb = 0; kb < K; kb += BK) {
        // load A tile into sa[k][m]
        if (!TA) {
#pragma unroll
            for (int i = 0; i < 2; i++) {
                int lin = tid + i * 256;
                int row = lin >> 3;
                int k4 = (lin & 7) * 4;
                float4 v = *(const float4*)(Ab + (long)(m0 + row) * lda + kb + k4);
                sa[k4 + 0][row] = v.x;
                sa[k4 + 1][row] = v.y;
                sa[k4 + 2][row] = v.z;
                sa[k4 + 3][row] = v.w;
            }
        } else {
#pragma unroll
            for (int i = 0; i < 2; i++) {
                int lin = tid + i * 256;
                int c4 = (lin & 15) * 4;
                int kk = lin >> 4;
                *(float4*)&sa[kk][c4] =
                    *(const float4*)(Ab + (long)(kb + kk) * lda + m0 + c4);
            }
        }
        // load B tile into sb[k][n]
        if (TB) {
#pragma unroll
            for (int i = 0; i < 2; i++) {
                int lin = tid + i * 256;
                int row = lin >> 3;
                int k4 = (lin & 7) * 4;
                float4 v = *(const float4*)(Bb + (long)(n0 + row) * ldb + kb + k4);
                sb[k4 + 0][row] = v.x;
                sb[k4 + 1][row] = v.y;
                sb[k4 + 2][row] = v.z;
                sb[k4 + 3][row] = v.w;
            }
        } else {
#pragma unroll
            for (int i = 0; i < 2; i++) {
                int lin = tid + i * 256;
                int c4 = (lin & 15) * 4;
                int kk = lin >> 4;
                *(float4*)&sb[kk][c4] =
                    *(const float4*)(Bb + (long)(kb + kk) * ldb + n0 + c4);
            }
        }
        __syncthreads();

#pragma unroll
        for (int kk = 0; kk < BK; kk++) {
            float4 a = *(const float4*)&sa[kk][tm * 4];
            float4 b = *(const float4*)&sb[kk][tn * 4];
            acc[0][0] += a.x * b.x; acc[0][1] += a.x * b.y;
            acc[0][2] += a.x * b.z; acc[0][3] += a.x * b.w;
            acc[1][0] += a.y * b.x; acc[1][1] += a.y * b.y;
            acc[1][2] += a.y * b.z; acc[1][3] += a.y * b.w;
            acc[2][0] += a.z * b.x; acc[2][1] += a.z * b.y;
            acc[2][2] += a.z * b.z; acc[2][3] += a.z * b.w;
            acc[3][0] += a.w * b.x; acc[3][1] += a.w * b.y;
            acc[3][2] += a.w * b.z; acc[3][3] += a.w * b.w;
        }
        __syncthreads();
    }

#pragma unroll
    for (int i = 0; i < 4; i++) {
        float4 st = make_float4(acc[i][0], acc[i][1], acc[i][2], acc[i][3]);
        *(float4*)(Cb + (long)(m0 + tm * 4 + i) * ldc + n0 + tn * 4) = st;
    }
}

// ---------------------------------------------------------------------------
// softmax over last axis of g_aw [64][1024][1024]; block = one row (256 thr)
// ---------------------------------------------------------------------------
__global__ void __launch_bounds__(256)
softmax_t_kernel(float* __restrict__ aw)
{
    const int t = blockIdx.x;
    const int bh = blockIdx.y;
    float4* row = reinterpret_cast<float4*>(aw + ((long)bh * Tt + t) * Tt);
    const int tid = threadIdx.x, lane = tid & 31, w = tid >> 5;
    __shared__ float red[8];
    __shared__ float bc;

    float4 v = row[tid];
    float m = fmaxf(fmaxf(v.x, v.y), fmaxf(v.z, v.w));
#pragma unroll
    for (int o = 16; o > 0; o >>= 1) m = fmaxf(m, __shfl_xor_sync(0xffffffffu, m, o));
    if (lane == 0) red[w] = m;
    __syncthreads();
    if (tid == 0) {
        float x = red[0];
#pragma unroll
        for (int i = 1; i < 8; i++) x = fmaxf(x, red[i]);
        bc = x;
    }
    __syncthreads();
    m = bc;

    float4 e;
    e.x = __expf(v.x - m); e.y = __expf(v.y - m);
    e.z = __expf(v.z - m); e.w = __expf(v.w - m);
    float s = e.x + e.y + e.z + e.w;
#pragma unroll
    for (int o = 16; o > 0; o >>= 1) s += __shfl_xor_sync(0xffffffffu, s, o);
    __syncthreads();
    if (lane == 0) red[w] = s;
    __syncthreads();
    if (tid == 0) {
        float x = 0.f;
#pragma unroll
        for (int i = 0; i < 8; i++) x += red[i];
        bc = 1.f / x;
    }
    __syncthreads();
    float inv = bc;
    e.x *= inv; e.y *= inv; e.z *= inv; e.w *= inv;
    row[tid] = e;
}

// softmax over last axis of g_pf [64*128][128]; block = one row (128 thr)
__global__ void __launch_bounds__(128)
softmax_f_kernel(float* __restrict__ pf)
{
    float* row = pf + (long)blockIdx.x * Ff;
    const int tid = threadIdx.x, lane = tid & 31, w = tid >> 5;
    __shared__ float red[4];
    __shared__ float bc;

    float v = row[tid];
    float m = v;
#pragma unroll
    for (int o = 16; o > 0; o >>= 1) m = fmaxf(m, __shfl_xor_sync(0xffffffffu, m, o));
    if (lane == 0) red[w] = m;
    __syncthreads();
    if (tid == 0) bc = fmaxf(fmaxf(red[0], red[1]), fmaxf(red[2], red[3]));
    __syncthreads();
    m = bc;

    float e = __expf(v - m);
    float s = e;
#pragma unroll
    for (int o = 16; o > 0; o >>= 1) s += __shfl_xor_sync(0xffffffffu, s, o);
    __syncthreads();
    if (lane == 0) red[w] = s;
    __syncthreads();
    if (tid == 0) bc = 1.f / (red[0] + red[1] + red[2] + red[3]);
    __syncthreads();
    row[tid] = e * bc;
}

// aw_avg[b][t][s] = mean_h aw[b*16+h][t][s]
__global__ void __launch_bounds__(256)
aw_avg_kernel(const float* __restrict__ aw, float* __restrict__ o)
{
    const int t = blockIdx.x;
    const int b = blockIdx.y;
    const float* base = aw + (((long)b * Hh) * Tt + t) * Tt;
    float* op = o + ((long)b * Tt + t) * Tt;
    for (int s = threadIdx.x; s < Tt; s += 256) {
        float acc = 0.f;
#pragma unroll
        for (int h = 0; h < Hh; h++) acc += base[(long)h * Tt * Tt + s];
        op[s] = acc * (1.f / 16.f);
    }
}

// ---------------------------------------------------------------------------
extern "C" void kernel_launch(void* const* d_in, const int* in_sizes, int n_in,
                              void* d_out, int out_size)
{
    const float* query = (const float*)d_in[0];
    const float* in_w  = (const float*)d_in[1];
    const float* in_b  = (const float*)d_in[2];
    const float* out_w = (const float*)d_in[3];
    const float* out_b = (const float*)d_in[4];

    float* out    = (float*)d_out;                                  // [4,128,1024,128]
    float* aw_avg = out + (long)Bsz * 128 * Tt * Ff;                // [4,1024,1024]

    float *q, *k, *v, *aw, *attn, *pf;
    cudaGetSymbolAddress((void**)&q,    g_q);
    cudaGetSymbolAddress((void**)&k,    g_k);
    cudaGetSymbolAddress((void**)&v,    g_v);
    cudaGetSymbolAddress((void**)&aw,   g_aw);
    cudaGetSymbolAddress((void**)&attn, g_attn);
    cudaGetSymbolAddress((void**)&pf,   g_pf);

    // 1. fused qkv 3x3 conv (+bias, scale q, relu)
    conv3x3_kernel<128, 3, 0><<<dim3(2, 64, 12), 256>>>(query, in_w, in_b, q, k, v);

    // 2. time-attention scores: aw[bh] = q[bh] @ k[bh]^T  (M=N=1024, K=128)
    gemm64_kernel<false, true, 0><<<dim3(16, 16, BH), 256>>>(
        q, k, aw, 1024, 1024, 128, 128, 128, 1024,
        (long)Tt * Ff, (long)Tt * Ff, (long)Tt * Tt, 0);

    // 3. row softmax in place
    softmax_t_kernel<<<dim3(1024, BH), 256>>>(aw);

    // 4. head-averaged attention weights -> output region 2
    aw_avg_kernel<<<dim3(1024, Bsz), 256>>>(aw, aw_avg);

    // 5. attn_t = aw @ v -> g_attn channels [0:16)
    gemm64_kernel<false, false, 1><<<dim3(2, 16, BH), 256>>>(
        aw, v, attn, 1024, 128, 1024, 1024, 128, 128,
        (long)Tt * Tt, (long)Tt * Ff, 0, 0);

    // 6. freq-attention scores: pf[bh] = q[bh]^T @ k[bh]  (M=N=128, K=1024)
    gemm64_kernel<true, false, 0><<<dim3(2, 2, BH), 256>>>(
        q, k, pf, 128, 128, 1024, 128, 128, 128,
        (long)Tt * Ff, (long)Tt * Ff, (long)Ff * Ff, 0);

    // 7. row softmax
    softmax_f_kernel<<<BH * Ff, 128>>>(pf);

    // 8. attn_f^T = v @ pf^T -> g_attn channels [16:32)
    gemm64_kernel<false, true, 1><<<dim3(2, 16, BH), 256>>>(
        v, pf, attn, 1024, 128, 128, 128, 128, 128,
        (long)Tt * Ff, (long)Ff * Ff, 0, 16);

    // 9. output conv (+bias, relu) -> output region 1
    conv3x3_kernel<32, 8, 1><<<dim3(2, 64, 32), 256>>>(attn, out_w, out_b, out,
                                                       nullptr, nullptr);
}

// round 4
// speedup vs baseline: 2.5932x; 2.5932x over previous
#include <cuda_runtime.h>
#include <cuda_bf16.h>
#include <cstdint>

#define Bsz 4
#define Hh  16
#define Tt  1024
#define Ff  128
#define BH  64

static const float SCALING = 0.08838834764831845f; // 128^-0.5

__device__ float g_q   [(long)BH * Tt * Ff];
__device__ float g_k   [(long)BH * Tt * Ff];
__device__ float g_v   [(long)BH * Tt * Ff];
__device__ float g_aw  [(long)BH * Tt * Tt];
__device__ float g_attn[(long)Bsz * 32 * Tt * Ff];
__device__ float g_pf  [(long)BH * Ff * Ff];

__device__ __forceinline__ float to_tf32(float x) {
    uint32_t u;
    asm("cvt.rna.tf32.f32 %0, %1;" : "=r"(u) : "f"(x));
    return __uint_as_float(u);
}
__device__ __forceinline__ void mma_tf32(float* d, float a0, float a1,
                                         float a2, float a3, float b0, float b1)
{
    asm volatile(
        "mma.sync.aligned.m16n8k8.row.col.f32.tf32.tf32.f32 "
        "{%0,%1,%2,%3}, {%4,%5,%6,%7}, {%8,%9}, {%0,%1,%2,%3};\n"
        : "+f"(d[0]), "+f"(d[1]), "+f"(d[2]), "+f"(d[3])
        : "r"(__float_as_uint(a0)), "r"(__float_as_uint(a1)),
          "r"(__float_as_uint(a2)), "r"(__float_as_uint(a3)),
          "r"(__float_as_uint(b0)), "r"(__float_as_uint(b1)));
}

// ---------------------------------------------------------------------------
// TF32 implicit-GEMM 3x3 conv (pad 1). Block: MT*16 couts x 512 spatial
// (4 t-rows x 128 f). 8 warps: warp = (t-row, f-half). K = CIN*9.
// EPI 0: qkv epilogue (mt 0->q scaled,1->k,2->v; bias+relu)
// EPI 1: relu(acc+bias) -> o0 [B,128,T,F], cout base = blockIdx.z*MT*16
// ---------------------------------------------------------------------------
template<int CIN, int MT, int EPI>
__global__ void __launch_bounds__(256)
conv_mma_kernel(const float* __restrict__ in, const float* __restrict__ w,
                const float* __restrict__ bias,
                float* __restrict__ o0, float* __restrict__ o1,
                float* __restrict__ o2)
{
    constexpr int WPAD = MT * 16 + 8;
    __shared__ float s_x[6][8][136];   // [trow][cin][3 + f + halo]
    __shared__ float s_w[9][8][WPAD];  // [tap][cin][cout]

    const int tid = threadIdx.x;
    const int warp = tid >> 5, lane = tid & 31;
    const int g = lane >> 2, tg = lane & 3;
    const int tt_w = warp >> 1;
    const int f0_w = (warp & 1) * 64;
    const int t0 = blockIdx.x * 4;
    const int b  = blockIdx.y;
    const int mg = blockIdx.z;

    if (tid < 96) { // zero halo cols (3 and 132), written once
        int r = tid / 16, c = (tid >> 1) & 7, col = (tid & 1) ? 132 : 3;
        s_x[r][c][col] = 0.f;
    }

    float acc[MT][8][4];
#pragma unroll
    for (int mt = 0; mt < MT; mt++)
#pragma unroll
        for (int i = 0; i < 8; i++)
#pragma unroll
            for (int j = 0; j < 4; j++) acc[mt][i][j] = 0.f;

    for (int cb = 0; cb < CIN; cb += 8) {
        __syncthreads();
#pragma unroll
        for (int it = 0; it < 6; it++) {      // 6 trow x 8 cin x 32 quads
            int idx = tid + it * 256;
            int v = idx & 31, rc = idx >> 5;
            int r = rc >> 3, c = rc & 7;
            int trow = t0 - 1 + r;
            float4 val = make_float4(0.f, 0.f, 0.f, 0.f);
            if ((unsigned)trow < 1024u)
                val = *(const float4*)(in +
                        (((long)(b * CIN + cb + c)) * 1024 + trow) * 128 + 4 * v);
            val.x = to_tf32(val.x); val.y = to_tf32(val.y);
            val.z = to_tf32(val.z); val.w = to_tf32(val.w);
            *(float4*)&s_x[r][c][4 + 4 * v] = val;
        }
        for (int idx = tid; idx < MT * 16 * 72; idx += 256) {
            int co = idx / 72, rem = idx % 72;
            int c = rem / 9, tap = rem % 9;
            s_w[tap][c][co] =
                to_tf32(w[((long)(mg * MT * 16 + co) * CIN + cb + c) * 9 + tap]);
        }
        __syncthreads();

#pragma unroll
        for (int tap = 0; tap < 9; tap++) {
            const int dt = tap / 3, df = tap % 3;
            float a[MT][4];
#pragma unroll
            for (int mt = 0; mt < MT; mt++) {
                a[mt][0] = s_w[tap][tg    ][mt * 16 + g];
                a[mt][1] = s_w[tap][tg    ][mt * 16 + g + 8];
                a[mt][2] = s_w[tap][tg + 4][mt * 16 + g];
                a[mt][3] = s_w[tap][tg + 4][mt * 16 + g + 8];
            }
            const float* xr = &s_x[tt_w + dt][0][0];
#pragma unroll
            for (int i = 0; i < 8; i++) {
                int col = 3 + f0_w + i * 8 + g + df;
                float b0 = xr[tg * 136 + col];
                float b1 = xr[(tg + 4) * 136 + col];
#pragma unroll
                for (int mt = 0; mt < MT; mt++)
                    mma_tf32(acc[mt][i], a[mt][0], a[mt][1], a[mt][2], a[mt][3],
                             b0, b1);
            }
        }
    }

    const int t = t0 + tt_w;
#pragma unroll
    for (int mt = 0; mt < MT; mt++) {
        if (EPI == 0) {
            float bv0 = bias[mt * 16 + g], bv1 = bias[mt * 16 + g + 8];
            const float sc = (mt == 0) ? SCALING : 1.f;
            float* dst = (mt == 0) ? o0 : (mt == 1) ? o1 : o2;
            long base0 = (((long)(b * Hh + g    )) * Tt + t) * Ff;
            long base1 = (((long)(b * Hh + g + 8)) * Tt + t) * Ff;
#pragma unroll
            for (int i = 0; i < 8; i++) {
                int f = f0_w + i * 8 + 2 * tg;
                float2 r0, r1;
                r0.x = fmaxf((acc[mt][i][0] + bv0) * sc, 0.f);
                r0.y = fmaxf((acc[mt][i][1] + bv0) * sc, 0.f);
                r1.x = fmaxf((acc[mt][i][2] + bv1) * sc, 0.f);
                r1.y = fmaxf((acc[mt][i][3] + bv1) * sc, 0.f);
                *(float2*)(dst + base0 + f) = r0;
                *(float2*)(dst + base1 + f) = r1;
            }
        } else {
            int co0 = mg * MT * 16 + mt * 16 + g, co1 = co0 + 8;
            float bv0 = bias[co0], bv1 = bias[co1];
            long base0 = (((long)(b * 128 + co0)) * Tt + t) * Ff;
            long base1 = (((long)(b * 128 + co1)) * Tt + t) * Ff;
#pragma unroll
            for (int i = 0; i < 8; i++) {
                int f = f0_w + i * 8 + 2 * tg;
                float2 r0, r1;
                r0.x = fmaxf(acc[mt][i][0] + bv0, 0.f);
                r0.y = fmaxf(acc[mt][i][1] + bv0, 0.f);
                r1.x = fmaxf(acc[mt][i][2] + bv1, 0.f);
                r1.y = fmaxf(acc[mt][i][3] + bv1, 0.f);
                *(float2*)(o0 + base0 + f) = r0;
                *(float2*)(o0 + base1 + f) = r1;
            }
        }
    }
}

// ---------------------------------------------------------------------------
// TF32 GEMM scores = q @ k^T. Block 128x128, K=128. 8 warps (4 wm x 2 wn).
// ---------------------------------------------------------------------------
__global__ void __launch_bounds__(256)
gemm_qk_kernel(const float* __restrict__ q, const float* __restrict__ kmat,
               float* __restrict__ aw)
{
    __shared__ float sA[128][36];
    __shared__ float sB[128][36];
    const int bh = blockIdx.z;
    const float* A = q    + (long)bh * Tt * Ff;
    const float* B = kmat + (long)bh * Tt * Ff;
    const int m0 = blockIdx.y * 128, n0 = blockIdx.x * 128;
    const int tid = threadIdx.x, warp = tid >> 5, lane = tid & 31;
    const int g = lane >> 2, tg = lane & 3;
    const int wm = warp >> 1, wn = warp & 1;

    float acc[2][8][4];
#pragma unroll
    for (int mt = 0; mt < 2; mt++)
#pragma unroll
        for (int i = 0; i < 8; i++)
#pragma unroll
            for (int j = 0; j < 4; j++) acc[mt][i][j] = 0.f;

    for (int kc = 0; kc < 128; kc += 32) {
        __syncthreads();
#pragma unroll
        for (int it = 0; it < 4; it++) {
            int idx = tid + it * 256;
            int row = idx >> 3, q4 = (idx & 7) * 4;
            float4 va = *(const float4*)(A + (long)(m0 + row) * Ff + kc + q4);
            float4 vb = *(const float4*)(B + (long)(n0 + row) * Ff + kc + q4);
            va.x = to_tf32(va.x); va.y = to_tf32(va.y);
            va.z = to_tf32(va.z); va.w = to_tf32(va.w);
            vb.x = to_tf32(vb.x); vb.y = to_tf32(vb.y);
            vb.z = to_tf32(vb.z); vb.w = to_tf32(vb.w);
            *(float4*)&sA[row][q4] = va;
            *(float4*)&sB[row][q4] = vb;
        }
        __syncthreads();
#pragma unroll
        for (int k8 = 0; k8 < 32; k8 += 8) {
            float a[2][4];
#pragma unroll
            for (int mt = 0; mt < 2; mt++) {
                int m = wm * 32 + mt * 16;
                a[mt][0] = sA[m + g    ][k8 + tg];
                a[mt][1] = sA[m + g + 8][k8 + tg];
                a[mt][2] = sA[m + g    ][k8 + tg + 4];
                a[mt][3] = sA[m + g + 8][k8 + tg + 4];
            }
#pragma unroll
            for (int i = 0; i < 8; i++) {
                int n = wn * 64 + i * 8 + g;
                float b0 = sB[n][k8 + tg];
                float b1 = sB[n][k8 + tg + 4];
#pragma unroll
                for (int mt = 0; mt < 2; mt++)
                    mma_tf32(acc[mt][i], a[mt][0], a[mt][1], a[mt][2], a[mt][3],
                             b0, b1);
            }
        }
    }

    float* C = aw + (long)bh * Tt * Tt;
#pragma unroll
    for (int mt = 0; mt < 2; mt++) {
        int m = m0 + wm * 32 + mt * 16;
#pragma unroll
        for (int i = 0; i < 8; i++) {
            int n = n0 + wn * 64 + i * 8 + 2 * tg;
            *(float2*)(C + (long)(m + g    ) * Tt + n) =
                make_float2(acc[mt][i][0], acc[mt][i][1]);
            *(float2*)(C + (long)(m + g + 8) * Tt + n) =
                make_float2(acc[mt][i][2], acc[mt][i][3]);
        }
    }
}

// ---------------------------------------------------------------------------
// TF32 GEMM attn_t = aw @ v. M=1024, N=128(full), K=1024.
// ---------------------------------------------------------------------------
__global__ void __launch_bounds__(256)
gemm_av_kernel(const float* __restrict__ aw, const float* __restrict__ v,
               float* __restrict__ attn)
{
    __shared__ float sA[128][36];
    __shared__ float sB[32][136];
    const int bh = blockIdx.y;
    const float* A = aw + (long)bh * Tt * Tt;
    const float* B = v  + (long)bh * Tt * Ff;
    const int m0 = blockIdx.x * 128;
    const int tid = threadIdx.x, warp = tid >> 5, lane = tid & 31;
    const int g = lane >> 2, tg = lane & 3;
    const int wm = warp >> 1, wn = warp & 1;

    float acc[2][8][4];
#pragma unroll
    for (int mt = 0; mt < 2; mt++)
#pragma unroll
        for (int i = 0; i < 8; i++)
#pragma unroll
            for (int j = 0; j < 4; j++) acc[mt][i][j] = 0.f;

    for (int kc = 0; kc < 1024; kc += 32) {
        __syncthreads();
#pragma unroll
        for (int it = 0; it < 4; it++) {
            int idx = tid + it * 256;
            int row = idx >> 3, q4 = (idx & 7) * 4;
            float4 va = *(const float4*)(A + (long)(m0 + row) * Tt + kc + q4);
            va.x = to_tf32(va.x); va.y = to_tf32(va.y);
            va.z = to_tf32(va.z); va.w = to_tf32(va.w);
            *(float4*)&sA[row][q4] = va;

            int kr = idx >> 5, vv = (idx & 31) * 4;
            float4 vb = *(const float4*)(B + (long)(kc + kr) * Ff + vv);
            vb.x = to_tf32(vb.x); vb.y = to_tf32(vb.y);
            vb.z = to_tf32(vb.z); vb.w = to_tf32(vb.w);
            *(float4*)&sB[kr][vv] = vb;
        }
        __syncthreads();
#pragma unroll
        for (int k8 = 0; k8 < 32; k8 += 8) {
            float a[2][4];
#pragma unroll
            for (int mt = 0; mt < 2; mt++) {
                int m = wm * 32 + mt * 16;
                a[mt][0] = sA[m + g    ][k8 + tg];
                a[mt][1] = sA[m + g + 8][k8 + tg];
                a[mt][2] = sA[m + g    ][k8 + tg + 4];
                a[mt][3] = sA[m + g + 8][k8 + tg + 4];
            }
#pragma unroll
            for (int i = 0; i < 8; i++) {
                int n = wn * 64 + i * 8 + g;
                float b0 = sB[k8 + tg    ][n];
                float b1 = sB[k8 + tg + 4][n];
#pragma unroll
                for (int mt = 0; mt < 2; mt++)
                    mma_tf32(acc[mt][i], a[mt][0], a[mt][1], a[mt][2], a[mt][3],
                             b0, b1);
            }
        }
    }

    const int b = bh >> 4, h = bh & 15;
    float* C = attn + ((long)(b * 32 + h)) * Tt * Ff;
#pragma unroll
    for (int mt = 0; mt < 2; mt++) {
        int m = m0 + wm * 32 + mt * 16;
#pragma unroll
        for (int i = 0; i < 8; i++) {
            int n = wn * 64 + i * 8 + 2 * tg;
            *(float2*)(C + (long)(m + g    ) * Ff + n) =
                make_float2(acc[mt][i][0], acc[mt][i][1]);
            *(float2*)(C + (long)(m + g + 8) * Ff + n) =
                make_float2(acc[mt][i][2], acc[mt][i][3]);
        }
    }
}

// ---------------------------------------------------------------------------
// fp32 SGEMM for the small freq path (unchanged from R1)
// ---------------------------------------------------------------------------
template<bool TA, bool TB, int CMODE>
__global__ void __launch_bounds__(256)
gemm64_kernel(const float* __restrict__ A, const float* __restrict__ B,
              float* __restrict__ C,
              int M, int N, int K, int lda, int ldb, int ldc,
              long sA, long sB, long sC, int chOff)
{
    constexpr int BM = 64, BN = 64, BK = 32;
    __shared__ float sa[BK][BM + 4];
    __shared__ float sb[BK][BN + 4];

    const int z = blockIdx.z;
    const float* Ab = A + (long)z * sA;
    const float* Bb = B + (long)z * sB;
    float* Cb;
    if (CMODE == 0) Cb = C + (long)z * sC;
    else {
        int b = z >> 4, h = z & 15;
        Cb = C + ((long)(b * 32 + chOff + h)) * Tt * Ff;
    }

    const int n0 = blockIdx.x * BN, m0 = blockIdx.y * BM;
    const int tid = threadIdx.x, tm = tid >> 4, tn = tid & 15;

    float acc[4][4];
#pragma unroll
    for (int i = 0; i < 4; i++)
#pragma unroll
        for (int j = 0; j < 4; j++) acc[i][j] = 0.f;

    for (int kb = 0; kb < K; kb += BK) {
        if (!TA) {
#pragma unroll
            for (int i = 0; i < 2; i++) {
                int lin = tid + i * 256;
                int row = lin >> 3, k4 = (lin & 7) * 4;
                float4 v = *(const float4*)(Ab + (long)(m0 + row) * lda + kb + k4);
                sa[k4 + 0][row] = v.x; sa[k4 + 1][row] = v.y;
                sa[k4 + 2][row] = v.z; sa[k4 + 3][row] = v.w;
            }
        } else {
#pragma unroll
            for (int i = 0; i < 2; i++) {
                int lin = tid + i * 256;
                int c4 = (lin & 15) * 4, kk = lin >> 4;
                *(float4*)&sa[kk][c4] =
                    *(const float4*)(Ab + (long)(kb + kk) * lda + m0 + c4);
            }
        }
        if (TB) {
#pragma unroll
            for (int i = 0; i < 2; i++) {
                int lin = tid + i * 256;
                int row = lin >> 3, k4 = (lin & 7) * 4;
                float4 v = *(const float4*)(Bb + (long)(n0 + row) * ldb + kb + k4);
                sb[k4 + 0][row] = v.x; sb[k4 + 1][row] = v.y;
                sb[k4 + 2][row] = v.z; sb[k4 + 3][row] = v.w;
            }
        } else {
#pragma unroll
            for (int i = 0; i < 2; i++) {
                int lin = tid + i * 256;
                int c4 = (lin & 15) * 4, kk = lin >> 4;
                *(float4*)&sb[kk][c4] =
                    *(const float4*)(Bb + (long)(kb + kk) * ldb + n0 + c4);
            }
        }
        __syncthreads();
#pragma unroll
        for (int kk = 0; kk < BK; kk++) {
            float4 a = *(const float4*)&sa[kk][tm * 4];
            float4 b = *(const float4*)&sb[kk][tn * 4];
            acc[0][0] += a.x * b.x; acc[0][1] += a.x * b.y;
            acc[0][2] += a.x * b.z; acc[0][3] += a.x * b.w;
            acc[1][0] += a.y * b.x; acc[1][1] += a.y * b.y;
            acc[1][2] += a.y * b.z; acc[1][3] += a.y * b.w;
            acc[2][0] += a.z * b.x; acc[2][1] += a.z * b.y;
            acc[2][2] += a.z * b.z; acc[2][3] += a.z * b.w;
            acc[3][0] += a.w * b.x; acc[3][1] += a.w * b.y;
            acc[3][2] += a.w * b.z; acc[3][3] += a.w * b.w;
        }
        __syncthreads();
    }
#pragma unroll
    for (int i = 0; i < 4; i++)
        *(float4*)(Cb + (long)(m0 + tm * 4 + i) * ldc + n0 + tn * 4) =
            make_float4(acc[i][0], acc[i][1], acc[i][2], acc[i][3]);
}

// ---------------------------------------------------------------------------
__global__ void __launch_bounds__(256)
softmax_t_kernel(float* __restrict__ aw)
{
    const int t = blockIdx.x, bh = blockIdx.y;
    float4* row = reinterpret_cast<float4*>(aw + ((long)bh * Tt + t) * Tt);
    const int tid = threadIdx.x, lane = tid & 31, w = tid >> 5;
    __shared__ float red[8];
    __shared__ float bc;

    float4 v = row[tid];
    float m = fmaxf(fmaxf(v.x, v.y), fmaxf(v.z, v.w));
#pragma unroll
    for (int o = 16; o > 0; o >>= 1) m = fmaxf(m, __shfl_xor_sync(~0u, m, o));
    if (lane == 0) red[w] = m;
    __syncthreads();
    if (tid == 0) {
        float x = red[0];
#pragma unroll
        for (int i = 1; i < 8; i++) x = fmaxf(x, red[i]);
        bc = x;
    }
    __syncthreads();
    m = bc;

    float4 e;
    e.x = __expf(v.x - m); e.y = __expf(v.y - m);
    e.z = __expf(v.z - m); e.w = __expf(v.w - m);
    float s = e.x + e.y + e.z + e.w;
#pragma unroll
    for (int o = 16; o > 0; o >>= 1) s += __shfl_xor_sync(~0u, s, o);
    __syncthreads();
    if (lane == 0) red[w] = s;
    __syncthreads();
    if (tid == 0) {
        float x = 0.f;
#pragma unroll
        for (int i = 0; i < 8; i++) x += red[i];
        bc = 1.f / x;
    }
    __syncthreads();
    float inv = bc;
    e.x *= inv; e.y *= inv; e.z *= inv; e.w *= inv;
    row[tid] = e;
}

__global__ void __launch_bounds__(128)
softmax_f_kernel(float* __restrict__ pf)
{
    float* row = pf + (long)blockIdx.x * Ff;
    const int tid = threadIdx.x, lane = tid & 31, w = tid >> 5;
    __shared__ float red[4];
    __shared__ float bc;

    float v = row[tid];
    float m = v;
#pragma unroll
    for (int o = 16; o > 0; o >>= 1) m = fmaxf(m, __shfl_xor_sync(~0u, m, o));
    if (lane == 0) red[w] = m;
    __syncthreads();
    if (tid == 0) bc = fmaxf(fmaxf(red[0], red[1]), fmaxf(red[2], red[3]));
    __syncthreads();
    m = bc;
    float e = __expf(v - m);
    float s = e;
#pragma unroll
    for (int o = 16; o > 0; o >>= 1) s += __shfl_xor_sync(~0u, s, o);
    __syncthreads();
    if (lane == 0) red[w] = s;
    __syncthreads();
    if (tid == 0) bc = 1.f / (red[0] + red[1] + red[2] + red[3]);
    __syncthreads();
    row[tid] = e * bc;
}

__global__ void __launch_bounds__(256)
aw_avg_kernel(const float* __restrict__ aw, float* __restrict__ o)
{
    const int t = blockIdx.x, b = blockIdx.y;
    const float* base = aw + (((long)b * Hh) * Tt + t) * Tt;
    float* op = o + ((long)b * Tt + t) * Tt;
    for (int s = threadIdx.x; s < Tt; s += 256) {
        float acc = 0.f;
#pragma unroll
        for (int h = 0; h < Hh; h++) acc += base[(long)h * Tt * Tt + s];
        op[s] = acc * (1.f / 16.f);
    }
}

// ---------------------------------------------------------------------------
extern "C" void kernel_launch(void* const* d_in, const int* in_sizes, int n_in,
                              void* d_out, int out_size)
{
    const float* query = (const float*)d_in[0];
    const float* in_w  = (const float*)d_in[1];
    const float* in_b  = (const float*)d_in[2];
    const float* out_w = (const float*)d_in[3];
    const float* out_b = (const float*)d_in[4];

    float* out    = (float*)d_out;
    float* aw_avg = out + (long)Bsz * 128 * Tt * Ff;

    float *q, *k, *v, *aw, *attn, *pf;
    cudaGetSymbolAddress((void**)&q,    g_q);
    cudaGetSymbolAddress((void**)&k,    g_k);
    cudaGetSymbolAddress((void**)&v,    g_v);
    cudaGetSymbolAddress((void**)&aw,   g_aw);
    cudaGetSymbolAddress((void**)&attn, g_attn);
    cudaGetSymbolAddress((void**)&pf,   g_pf);

    // 1. fused qkv conv (tf32 mma): 48 couts per block (MT=3)
    conv_mma_kernel<128, 3, 0><<<dim3(256, 4, 1), 256>>>(query, in_w, in_b,
                                                         q, k, v);
    // 2. time scores (tf32 mma)
    gemm_qk_kernel<<<dim3(8, 8, BH), 256>>>(q, k, aw);
    // 3. softmax rows
    softmax_t_kernel<<<dim3(1024, BH), 256>>>(aw);
    // 4. head-avg weights -> out region 2
    aw_avg_kernel<<<dim3(1024, Bsz), 256>>>(aw, aw_avg);
    // 5. attn_t = aw @ v (tf32 mma) -> channels [0:16)
    gemm_av_kernel<<<dim3(8, BH), 256>>>(aw, v, attn);
    // 6. freq scores pf = q^T @ k (fp32)
    gemm64_kernel<true, false, 0><<<dim3(2, 2, BH), 256>>>(
        q, k, pf, 128, 128, 1024, 128, 128, 128,
        (long)Tt * Ff, (long)Tt * Ff, (long)Ff * Ff, 0);
    // 7. softmax
    softmax_f_kernel<<<BH * Ff, 128>>>(pf);
    // 8. attn_f^T = v @ pf^T (fp32) -> channels [16:32)
    gemm64_kernel<false, true, 1><<<dim3(2, 16, BH), 256>>>(
        v, pf, attn, 1024, 128, 128, 128, 128, 128,
        (long)Tt * Ff, (long)Ff * Ff, 0, 16);
    // 9. output conv (tf32 mma): 32 couts per block (MT=2), 4 groups
    conv_mma_kernel<32, 2, 1><<<dim3(256, 4, 4), 256>>>(attn, out_w, out_b,
                                                        out, nullptr, nullptr);
}